// round 14
// baseline (speedup 1.0000x reference)
#include <cuda_runtime.h>
#include <cuda_fp16.h>
#include <cstddef>
#include <cstdint>

typedef unsigned long long ull;
typedef unsigned int uint;

// ---------------------------------------------------------------------------
// Problem constants
// ---------------------------------------------------------------------------
#define NC 100000
#define NM 50000
#define ND 10000

#define OFF_WORDS 320008ull
#define CSR_WORDS 4800000ull
#define P_WORDS   10240000ull      // P: 320k rows x 64 fp16 (counted in 4B words)
#define AGG_WORDS 10240000ull      // AGG: 160k rows x 64 fp32
#define HH_WORDS  5120000ull       // H: 160k rows x 64 fp16
#define SCRATCH_WORDS (OFF_WORDS + CSR_WORDS + P_WORDS + AGG_WORDS + HH_WORDS)
__device__ __align__(16) float g_scratch[SCRATCH_WORDS];

// ---------------------------------------------------------------------------
// f32x2 helpers (gather path)
// ---------------------------------------------------------------------------
__device__ __forceinline__ ull splat2(float x) {
    ull r; asm("mov.b64 %0, {%1, %1};" : "=l"(r) : "f"(x)); return r;
}
__device__ __forceinline__ ull pack2(float lo, float hi) {
    ull r; asm("mov.b64 %0, {%1, %2};" : "=l"(r) : "f"(lo), "f"(hi)); return r;
}
__device__ __forceinline__ ull add2(ull a, ull b) {
    ull r; asm("add.rn.f32x2 %0, %1, %2;" : "=l"(r) : "l"(a), "l"(b)); return r;
}
__device__ __forceinline__ ull mul2(ull a, ull b) {
    ull r; asm("mul.rn.f32x2 %0, %1, %2;" : "=l"(r) : "l"(a), "l"(b)); return r;
}
__device__ __forceinline__ ull h2_to_f2(uint h) {
    __half2 hv = *reinterpret_cast<__half2*>(&h);
    float2 f = __half22float2(hv);
    return pack2(f.x, f.y);
}

// ---------------------------------------------------------------------------
// mma / ldmatrix primitives
// ---------------------------------------------------------------------------
__device__ __forceinline__ void mma16816(float* c, const uint* a, const uint* b) {
    asm volatile(
        "mma.sync.aligned.m16n8k16.row.col.f32.f16.f16.f32 "
        "{%0,%1,%2,%3}, {%4,%5,%6,%7}, {%8,%9}, {%0,%1,%2,%3};"
        : "+f"(c[0]), "+f"(c[1]), "+f"(c[2]), "+f"(c[3])
        : "r"(a[0]), "r"(a[1]), "r"(a[2]), "r"(a[3]), "r"(b[0]), "r"(b[1]));
}
__device__ __forceinline__ void ldsm_x4(uint* r, uint32_t addr) {
    asm volatile("ldmatrix.sync.aligned.m8n8.x4.shared.b16 {%0,%1,%2,%3}, [%4];"
                 : "=r"(r[0]), "=r"(r[1]), "=r"(r[2]), "=r"(r[3]) : "r"(addr));
}
__device__ __forceinline__ void ldsm_x4_t(uint* r, uint32_t addr) {
    asm volatile("ldmatrix.sync.aligned.m8n8.x4.trans.shared.b16 {%0,%1,%2,%3}, [%4];"
                 : "=r"(r[0]), "=r"(r[1]), "=r"(r[2]), "=r"(r[3]) : "r"(addr));
}
__device__ __forceinline__ uint32_t smem_u32(const void* p) {
    return (uint32_t)__cvta_generic_to_shared(p);
}

// ---------------------------------------------------------------------------
// CSR build kernels (8 edges per thread)
// ---------------------------------------------------------------------------
__global__ void zero_int_kernel(int* __restrict__ p, int n) {
    int i = blockIdx.x * blockDim.x + threadIdx.x;
    if (i < n) p[i] = 0;
}

struct Edge6 {
    const int* src[6]; const int* dst[6];
    int* off[6]; int* csr[6];
    int bs[7]; int E[6];
};

__global__ void count_all(Edge6 a) {
    int b = blockIdx.x, r = 0;
    while (b >= a.bs[r + 1]) r++;
    int e = ((b - a.bs[r]) * 256 + threadIdx.x) * 8;
    int E = a.E[r];
    int* off = a.off[r];
    if (e + 8 <= E) {
        int4 d0 = *(const int4*)(a.dst[r] + e);
        int4 d1 = *(const int4*)(a.dst[r] + e + 4);
        atomicAdd(&off[d0.x + 1], 1);
        atomicAdd(&off[d0.y + 1], 1);
        atomicAdd(&off[d0.z + 1], 1);
        atomicAdd(&off[d0.w + 1], 1);
        atomicAdd(&off[d1.x + 1], 1);
        atomicAdd(&off[d1.y + 1], 1);
        atomicAdd(&off[d1.z + 1], 1);
        atomicAdd(&off[d1.w + 1], 1);
    } else {
        for (; e < E; e++) atomicAdd(&off[a.dst[r][e] + 1], 1);
    }
}

// Cursor-free fill: consumes the exclusive offsets in-place.
// After this kernel, off[d] == original off[d+1] (segment end).
__global__ void fill_all(Edge6 a) {
    int b = blockIdx.x, r = 0;
    while (b >= a.bs[r + 1]) r++;
    int e = ((b - a.bs[r]) * 256 + threadIdx.x) * 8;
    int E = a.E[r];
    int* off = a.off[r];
    int* csr = a.csr[r];
    if (e + 8 <= E) {
        int4 d0 = *(const int4*)(a.dst[r] + e);
        int4 d1 = *(const int4*)(a.dst[r] + e + 4);
        int4 s0 = *(const int4*)(a.src[r] + e);
        int4 s1 = *(const int4*)(a.src[r] + e + 4);
        csr[atomicAdd(&off[d0.x], 1)] = s0.x;
        csr[atomicAdd(&off[d0.y], 1)] = s0.y;
        csr[atomicAdd(&off[d0.z], 1)] = s0.z;
        csr[atomicAdd(&off[d0.w], 1)] = s0.w;
        csr[atomicAdd(&off[d1.x], 1)] = s1.x;
        csr[atomicAdd(&off[d1.y], 1)] = s1.y;
        csr[atomicAdd(&off[d1.z], 1)] = s1.z;
        csr[atomicAdd(&off[d1.w], 1)] = s1.w;
    } else {
        for (; e < E; e++)
            csr[atomicAdd(&off[a.dst[r][e]], 1)] = a.src[r][e];
    }
}

struct ScanArgs { int* data[6]; int n[6]; };

// One block per relation; inclusive scan of data[0..n], 8 elems per thread.
__global__ __launch_bounds__(1024) void scan6(ScanArgs a) {
    __shared__ int wsum[33];
    int* data = a.data[blockIdx.x];
    int n = a.n[blockIdx.x];
    int t = threadIdx.x, lane = t & 31, wid = t >> 5;
    int carry = 0;
    for (int base = 0; base <= n; base += 8192) {
        int i0 = base + t * 8;
        int v[8], ps[8];
        #pragma unroll
        for (int j = 0; j < 8; j++)
            v[j] = (i0 + j <= n) ? data[i0 + j] : 0;
        ps[0] = v[0];
        #pragma unroll
        for (int j = 1; j < 8; j++) ps[j] = ps[j - 1] + v[j];
        int s = ps[7];
        int sc = s;
        #pragma unroll
        for (int o = 1; o < 32; o <<= 1) {
            int u = __shfl_up_sync(0xffffffffu, sc, o);
            if (lane >= o) sc += u;
        }
        if (lane == 31) wsum[wid] = sc;
        __syncthreads();
        if (wid == 0) {
            int w = wsum[lane];
            int wc = w;
            #pragma unroll
            for (int o = 1; o < 32; o <<= 1) {
                int u = __shfl_up_sync(0xffffffffu, wc, o);
                if (lane >= o) wc += u;
            }
            wsum[lane] = wc;
            if (lane == 31) wsum[32] = wc;
        }
        __syncthreads();
        int prefix = carry + (wid ? wsum[wid - 1] : 0) + (sc - s);
        #pragma unroll
        for (int j = 0; j < 8; j++)
            if (i0 + j <= n) data[i0 + j] = prefix + ps[j];
        carry += wsum[32];
        __syncthreads();
    }
}

// ---------------------------------------------------------------------------
// Merged dual-relation gather (fp16 rows), one warp per dst node, 8-wide MLP.
// Post-fill offsets: segment of w is [w? off[w-1] : 0, off[w]).   (R12 version)
// ---------------------------------------------------------------------------
__device__ __forceinline__ ull gather_rel(const __half* __restrict__ P,
                                          const int* __restrict__ off,
                                          const int* __restrict__ csr,
                                          int w, int lane, float& sc) {
    int s = w ? off[w - 1] : 0;
    int e = off[w];
    const uint* B = (const uint*)P + lane;
    ull a0 = 0ull, a1 = 0ull, a2 = 0ull, a3 = 0ull;
    int i = s;
    for (; i + 8 <= e; i += 8) {
        int s0 = csr[i],     s1 = csr[i + 1], s2 = csr[i + 2], s3 = csr[i + 3];
        int s4 = csr[i + 4], s5 = csr[i + 5], s6 = csr[i + 6], s7 = csr[i + 7];
        uint v0 = B[(size_t)s0 * 32];
        uint v1 = B[(size_t)s1 * 32];
        uint v2 = B[(size_t)s2 * 32];
        uint v3 = B[(size_t)s3 * 32];
        uint v4 = B[(size_t)s4 * 32];
        uint v5 = B[(size_t)s5 * 32];
        uint v6 = B[(size_t)s6 * 32];
        uint v7 = B[(size_t)s7 * 32];
        a0 = add2(a0, add2(h2_to_f2(v0), h2_to_f2(v1)));
        a1 = add2(a1, add2(h2_to_f2(v2), h2_to_f2(v3)));
        a2 = add2(a2, add2(h2_to_f2(v4), h2_to_f2(v5)));
        a3 = add2(a3, add2(h2_to_f2(v6), h2_to_f2(v7)));
    }
    for (; i < e; i++)
        a0 = add2(a0, h2_to_f2(B[(size_t)csr[i] * 32]));
    int deg = e - s;
    sc = 1.0f / (float)(deg > 1 ? deg : 1);
    return add2(add2(a0, a1), add2(a2, a3));
}

struct Gather3 {
    const __half* PA[3]; const int* offA[3]; const int* csrA[3];
    const __half* PB[3]; const int* offB[3]; const int* csrB[3];
    float* out[3]; int ws[4];
};

__global__ __launch_bounds__(256) void gather_all(Gather3 a) {
    int gw = (blockIdx.x * blockDim.x + threadIdx.x) >> 5;
    int lane = threadIdx.x & 31;
    if (gw >= a.ws[3]) return;
    int t = 0;
    while (gw >= a.ws[t + 1]) t++;
    int w = gw - a.ws[t];
    float scA, scB;
    ull accA = gather_rel(a.PA[t], a.offA[t], a.csrA[t], w, lane, scA);
    ull accB = gather_rel(a.PB[t], a.offB[t], a.csrB[t], w, lane, scB);
    ull res = add2(mul2(accA, splat2(scA)), mul2(accB, splat2(scB)));
    *(ull*)(a.out[t] + (size_t)w * 64 + lane * 2) = res;
}

// ---------------------------------------------------------------------------
// Tensor-core GEMM core, X dtype templated (float or __half source rows):
// acc += fp16(X[m0:m0+128, :kt*32]) @ fp16(wscale*(W0(+W1)))
// Block = 128 rows x 64 cols, 256 threads (8 warps x 16-row stripe).
// ---------------------------------------------------------------------------
#define XS 40
#define WS 72

template<typename T>
__device__ __forceinline__ void mma_tiles(
    const T* __restrict__ X, int ldx,
    const float* __restrict__ W0, const float* __restrict__ W1, float wscale,
    int ktiles, int m0, int M,
    __half Xh[][XS], __half Wh[][WS], float acc[8][4]) {

    const int t = threadIdx.x;
    const int lane = t & 31;
    const int wrow = (t >> 5) * 16;

    for (int kt = 0; kt < ktiles; kt++) {
        int kb = kt * 32;
        #pragma unroll
        for (int it = 0; it < 4; it++) {
            int idx = t + 256 * it;
            int row = idx >> 3, f4 = idx & 7;
            int m = m0 + row;
            if (sizeof(T) == 4) {
                float4 v = make_float4(0.f, 0.f, 0.f, 0.f);
                if (m < M) v = *(const float4*)((const float*)X + (size_t)m * ldx + kb + f4 * 4);
                __half2 h0 = __floats2half2_rn(v.x, v.y);
                __half2 h1 = __floats2half2_rn(v.z, v.w);
                uint2 st = { *(uint*)&h0, *(uint*)&h1 };
                *(uint2*)(&Xh[row][f4 * 4]) = st;
            } else {
                uint2 v = make_uint2(0u, 0u);
                if (m < M) v = *(const uint2*)((const __half*)X + (size_t)m * ldx + kb + f4 * 4);
                *(uint2*)(&Xh[row][f4 * 4]) = v;
            }
        }
        #pragma unroll
        for (int it = 0; it < 2; it++) {
            int idx = t + 256 * it;
            int kw = idx >> 4, f4 = idx & 15;
            const float* wp = W0 + (size_t)(kb + kw) * 64 + f4 * 4;
            float4 wv = *(const float4*)wp;
            if (W1) {
                float4 w2 = *(const float4*)(W1 + (size_t)(kb + kw) * 64 + f4 * 4);
                wv.x += w2.x; wv.y += w2.y; wv.z += w2.z; wv.w += w2.w;
            }
            wv.x *= wscale; wv.y *= wscale; wv.z *= wscale; wv.w *= wscale;
            __half2 h0 = __floats2half2_rn(wv.x, wv.y);
            __half2 h1 = __floats2half2_rn(wv.z, wv.w);
            uint2 st = { *(uint*)&h0, *(uint*)&h1 };
            *(uint2*)(&Wh[kw][f4 * 4]) = st;
        }
        __syncthreads();

        #pragma unroll
        for (int ks = 0; ks < 2; ks++) {
            int k = ks * 16;
            uint a[4];
            ldsm_x4(a, smem_u32(&Xh[wrow + (lane & 15)][k + (lane >> 4) * 8]));
            int i8 = lane & 7, sel = lane >> 3;
            #pragma unroll
            for (int jj = 0; jj < 4; jj++) {
                uint b[4];
                ldsm_x4_t(b, smem_u32(
                    &Wh[k + i8 + (sel & 1) * 8][jj * 16 + (sel >> 1) * 8]));
                mma16816(acc[jj * 2],     a, b);
                mma16816(acc[jj * 2 + 1], a, b + 2);
            }
        }
        __syncthreads();
    }
}

// ---------------------------------------------------------------------------
// proj_all: 6 independent projections Y[r] = fp16(X[r] @ W[r])
// ---------------------------------------------------------------------------
template<typename T>
struct Proj6 { const T* X[6]; const float* W[6]; __half* Y[6]; int M[6]; int bs[7]; };

template<int KT, typename T>
__global__ __launch_bounds__(256) void proj_all(Proj6<T> a) {
    __shared__ __half Xh[128][XS];
    __shared__ __half Wh[32][WS];
    int b = blockIdx.x, r = 0;
    while (b >= a.bs[r + 1]) r++;
    int m0 = (b - a.bs[r]) * 128;
    int M = a.M[r];

    float acc[8][4];
    #pragma unroll
    for (int i = 0; i < 8; i++)
        #pragma unroll
        for (int j = 0; j < 4; j++) acc[i][j] = 0.f;

    mma_tiles<T>(a.X[r], KT * 32, a.W[r], nullptr, 1.0f, KT, m0, M, Xh, Wh, acc);

    const int lane = threadIdx.x & 31;
    const int wrow = (threadIdx.x >> 5) * 16;
    const int q2 = (lane & 3) * 2;
    __half* Y = a.Y[r];
    #pragma unroll
    for (int half = 0; half < 2; half++) {
        int m = m0 + wrow + (lane >> 2) + half * 8;
        int off = half * 2;
        if (m < M) {
            #pragma unroll
            for (int j = 0; j < 8; j++) {
                __half2 h = __floats2half2_rn(acc[j][off], acc[j][off + 1]);
                *(uint*)(Y + (size_t)m * 64 + j * 8 + q2) = *(uint*)&h;
            }
        }
    }
}

// ---------------------------------------------------------------------------
// combine1_all: H(fp16) = relu(x @ 0.5(Wa+Wb) + 0.5*(AGG + ba + bb))
// ---------------------------------------------------------------------------
struct Comb3 {
    const float* X[3]; const float* Wa[3]; const float* Wb[3];
    const float* ba[3]; const float* bb[3]; const float* AGG[3];
    __half* Y[3]; int M[3]; int bs[4];
};

__global__ __launch_bounds__(256) void combine1_all(Comb3 a) {
    __shared__ __half Xh[128][XS];
    __shared__ __half Wh[32][WS];
    int b = blockIdx.x, t3 = 0;
    while (b >= a.bs[t3 + 1]) t3++;
    int m0 = (b - a.bs[t3]) * 128;
    int M = a.M[t3];

    float acc[8][4];
    #pragma unroll
    for (int i = 0; i < 8; i++)
        #pragma unroll
        for (int j = 0; j < 4; j++) acc[i][j] = 0.f;

    mma_tiles<float>(a.X[t3], 128, a.Wa[t3], a.Wb[t3], 0.5f, 4, m0, M, Xh, Wh, acc);

    const int lane = threadIdx.x & 31;
    const int wrow = (threadIdx.x >> 5) * 16;
    const int q2 = (lane & 3) * 2;
    const float* AGG = a.AGG[t3];
    __half* Y = a.Y[t3];
    float cb[8][2];
    #pragma unroll
    for (int j = 0; j < 8; j++) {
        int c = j * 8 + q2;
        cb[j][0] = 0.5f * (a.ba[t3][c] + a.bb[t3][c]);
        cb[j][1] = 0.5f * (a.ba[t3][c + 1] + a.bb[t3][c + 1]);
    }
    #pragma unroll
    for (int half = 0; half < 2; half++) {
        int m = m0 + wrow + (lane >> 2) + half * 8;
        int off = half * 2;
        if (m < M) {
            size_t base = (size_t)m * 64;
            #pragma unroll
            for (int j = 0; j < 8; j++) {
                int c = j * 8 + q2;
                float2 g = *(const float2*)(AGG + base + c);
                float ox = fmaxf(acc[j][off]     + 0.5f * g.x + cb[j][0], 0.f);
                float oy = fmaxf(acc[j][off + 1] + 0.5f * g.y + cb[j][1], 0.f);
                __half2 h = __floats2half2_rn(ox, oy);
                *(uint*)(Y + base + c) = *(uint*)&h;
            }
        }
    }
}

// ---------------------------------------------------------------------------
// final_all: O = l2norm( H @ 0.5(W2a+W2b) + 0.5*(AGG + b2a + b2b) + x@Wr + br )
// H is fp16.
// ---------------------------------------------------------------------------
struct Final3 {
    const __half* Hs[3]; const float* W2a[3]; const float* W2b[3];
    const float* b2a[3]; const float* b2b[3]; const float* AGG[3];
    const float* Xr[3]; const float* Wr[3]; const float* br[3];
    float* Y[3]; int M[3]; int bs[4];
};

__global__ __launch_bounds__(256) void final_all(Final3 a) {
    __shared__ __half Xh[128][XS];
    __shared__ __half Wh[32][WS];
    int b = blockIdx.x, t3 = 0;
    while (b >= a.bs[t3 + 1]) t3++;
    int m0 = (b - a.bs[t3]) * 128;
    int M = a.M[t3];

    float acc[8][4];
    #pragma unroll
    for (int i = 0; i < 8; i++)
        #pragma unroll
        for (int j = 0; j < 4; j++) acc[i][j] = 0.f;

    mma_tiles<__half>(a.Hs[t3], 64,  a.W2a[t3], a.W2b[t3], 0.5f, 2, m0, M, Xh, Wh, acc);
    mma_tiles<float>(a.Xr[t3], 128, a.Wr[t3],  nullptr,   1.0f, 4, m0, M, Xh, Wh, acc);

    const int lane = threadIdx.x & 31;
    const int wrow = (threadIdx.x >> 5) * 16;
    const int q2 = (lane & 3) * 2;
    const float* AGG = a.AGG[t3];
    float* Y = a.Y[t3];
    float cb[8][2];
    #pragma unroll
    for (int j = 0; j < 8; j++) {
        int c = j * 8 + q2;
        cb[j][0] = 0.5f * (a.b2a[t3][c] + a.b2b[t3][c]) + a.br[t3][c];
        cb[j][1] = 0.5f * (a.b2a[t3][c + 1] + a.b2b[t3][c + 1]) + a.br[t3][c + 1];
    }
    #pragma unroll
    for (int half = 0; half < 2; half++) {
        int m = m0 + wrow + (lane >> 2) + half * 8;
        int off = half * 2;
        bool ok = (m < M);
        size_t base = (size_t)m * 64;
        float v[8][2];
        float ss = 0.f;
        if (ok) {
            #pragma unroll
            for (int j = 0; j < 8; j++) {
                int c = j * 8 + q2;
                float2 g = *(const float2*)(AGG + base + c);
                v[j][0] = acc[j][off]     + 0.5f * g.x + cb[j][0];
                v[j][1] = acc[j][off + 1] + 0.5f * g.y + cb[j][1];
                ss += v[j][0] * v[j][0] + v[j][1] * v[j][1];
            }
        }
        ss += __shfl_xor_sync(0xffffffffu, ss, 1);
        ss += __shfl_xor_sync(0xffffffffu, ss, 2);
        if (ok) {
            float inv = 1.0f / fmaxf(sqrtf(ss), 1e-12f);
            #pragma unroll
            for (int j = 0; j < 8; j++) {
                float2 o = make_float2(v[j][0] * inv, v[j][1] * inv);
                *(float2*)(Y + base + j * 8 + q2) = o;
            }
        }
    }
}

// ---------------------------------------------------------------------------
// Host orchestration
// ---------------------------------------------------------------------------
extern "C" void kernel_launch(void* const* d_in, const int* in_sizes, int n_in,
                              void* d_out, int out_size) {
    static cudaStream_t s1 = [] {
        cudaStream_t s; cudaStreamCreateWithFlags(&s, cudaStreamNonBlocking); return s; }();
    static cudaEvent_t evFork = [] {
        cudaEvent_t e; cudaEventCreateWithFlags(&e, cudaEventDisableTiming); return e; }();
    static cudaEvent_t evJoin = [] {
        cudaEvent_t e; cudaEventCreateWithFlags(&e, cudaEventDisableTiming); return e; }();

    const float* xc = (const float*)d_in[0];
    const float* xm = (const float*)d_in[1];
    const float* xd = (const float*)d_in[2];
    // relation order: 0=c->m, 1=m->d, 2=c->d, 3=m->c, 4=d->m, 5=d->c
    const int srcIdx[6] = {3, 5, 7, 9, 11, 13};
    const int dstIdx[6] = {4, 6, 8, 10, 12, 14};
    const int* SRC[6]; const int* DST[6]; int EE[6];
    for (int r = 0; r < 6; r++) {
        SRC[r] = (const int*)d_in[srcIdx[r]];
        DST[r] = (const int*)d_in[dstIdx[r]];
        EE[r]  = in_sizes[srcIdx[r]];
    }
    const float* W1l  = (const float*)d_in[15];
    const float* W1r  = (const float*)d_in[16];
    const float* b1   = (const float*)d_in[17];
    const float* W2l  = (const float*)d_in[18];
    const float* W2r  = (const float*)d_in[19];
    const float* b2   = (const float*)d_in[20];
    const float* Wres = (const float*)d_in[21];
    const float* bres = (const float*)d_in[22];
    float* out = (float*)d_out;

    const int NSRC[6]    = {NC, NM, NC, NM, ND, ND};
    const int NDSTA[6]   = {NM, ND, ND, NC, NM, NC};
    const int srcType[6] = {0, 1, 0, 1, 2, 2};

    float* S = nullptr;
    cudaGetSymbolAddress((void**)&S, g_scratch);

    int*    OFF = (int*)S;
    int*    CSR = OFF + OFF_WORDS;
    __half* P   = (__half*)(CSR + CSR_WORDS);
    float*  AGG = (float*)(CSR + CSR_WORDS) + P_WORDS;
    __half* H   = (__half*)(AGG + AGG_WORDS);

    int* offR[6]; int* csrR[6]; __half* PR[6];
    {
        size_t o = 0, e = 0, p = 0;
        for (int r = 0; r < 6; r++) {
            offR[r] = OFF + o;  o += (size_t)NDSTA[r] + 1;
            csrR[r] = CSR + e;  e += (size_t)EE[r];
            PR[r]   = P + p;    p += (size_t)NSRC[r] * 64;
        }
    }

    float* AGGm = AGG;
    float* AGGd = AGGm + (size_t)NM * 64;
    float* AGGc = AGGd + (size_t)ND * 64;
    __half* Hc = H;
    __half* Hm = Hc + (size_t)NC * 64;
    __half* Hd = Hm + (size_t)NM * 64;
    const float* X1[3] = {xc, xm, xd};
    const __half* HX[3] = {Hc, Hm, Hd};
    float* Oc = out;
    float* Om = Oc + (size_t)NC * 64;
    float* Od = Om + (size_t)NM * 64;

    // ---- fork: CSR build on side stream ----
    cudaEventRecord(evFork, 0);
    cudaStreamWaitEvent(s1, evFork, 0);
    {
        int nz = (int)OFF_WORDS;
        zero_int_kernel<<<(nz + 255) / 256, 256, 0, s1>>>(OFF, nz);
    }
    Edge6 ea;
    {
        int cum = 0;
        for (int r = 0; r < 6; r++) {
            ea.src[r] = SRC[r]; ea.dst[r] = DST[r];
            ea.off[r] = offR[r]; ea.csr[r] = csrR[r];
            ea.E[r] = EE[r];
            ea.bs[r] = cum; cum += (EE[r] + 2047) / 2048;
        }
        ea.bs[6] = cum;
    }
    count_all<<<ea.bs[6], 256, 0, s1>>>(ea);
    {
        ScanArgs sa;
        for (int r = 0; r < 6; r++) { sa.data[r] = offR[r]; sa.n[r] = NDSTA[r]; }
        scan6<<<6, 1024, 0, s1>>>(sa);
    }
    fill_all<<<ea.bs[6], 256, 0, s1>>>(ea);
    cudaEventRecord(evJoin, s1);

    // ---- layer 1: projections (concurrent with CSR build) ----
    Proj6<float> p1;
    {
        int cum = 0;
        for (int r = 0; r < 6; r++) {
            p1.X[r] = X1[srcType[r]];
            p1.W[r] = W1l + (size_t)r * 8192;
            p1.Y[r] = PR[r];
            p1.M[r] = NSRC[r];
            p1.bs[r] = cum; cum += (NSRC[r] + 127) / 128;
        }
        p1.bs[6] = cum;
    }
    proj_all<4, float><<<p1.bs[6], 256>>>(p1);

    cudaStreamWaitEvent(0, evJoin, 0);

    // relation pairing per dst type: t=0 m <- (0,4); t=1 d <- (1,2); t=2 c <- (3,5)
    const int relA[3] = {0, 1, 3};
    const int relB[3] = {4, 2, 5};
    float* AGGt[3] = {AGGm, AGGd, AGGc};
    const int NT[3] = {NM, ND, NC};
    Gather3 ga;
    {
        int cum = 0;
        for (int t = 0; t < 3; t++) {
            ga.offA[t] = offR[relA[t]]; ga.csrA[t] = csrR[relA[t]];
            ga.offB[t] = offR[relB[t]]; ga.csrB[t] = csrR[relB[t]];
            ga.PA[t] = PR[relA[t]]; ga.PB[t] = PR[relB[t]];
            ga.out[t] = AGGt[t];
            ga.ws[t] = cum; cum += NT[t];
        }
        ga.ws[3] = cum;
    }
    const int gatherBlocks = ((NM + ND + NC) * 32 + 255) / 256;

    gather_all<<<gatherBlocks, 256>>>(ga);

    // ---- layer 1: combines (H in fp16) ----
    const float* XD[3] = {xm, xd, xc};
    __half* HT[3] = {Hm, Hd, Hc};
    Comb3 c1;
    {
        int cum = 0;
        for (int t = 0; t < 3; t++) {
            c1.X[t]  = XD[t];
            c1.Wa[t] = W1r + (size_t)relA[t] * 8192;
            c1.Wb[t] = W1r + (size_t)relB[t] * 8192;
            c1.ba[t] = b1 + (size_t)relA[t] * 64;
            c1.bb[t] = b1 + (size_t)relB[t] * 64;
            c1.AGG[t] = AGGt[t];
            c1.Y[t] = HT[t];
            c1.M[t] = NT[t];
            c1.bs[t] = cum; cum += (NT[t] + 127) / 128;
        }
        c1.bs[3] = cum;
    }
    combine1_all<<<c1.bs[3], 256>>>(c1);

    // ---- layer 2: projections (X = fp16 H) ----
    Proj6<__half> p2;
    {
        int cum = 0;
        for (int r = 0; r < 6; r++) {
            p2.X[r] = HX[srcType[r]];
            p2.W[r] = W2l + (size_t)r * 4096;
            p2.Y[r] = PR[r];
            p2.M[r] = NSRC[r];
            p2.bs[r] = cum; cum += (NSRC[r] + 127) / 128;
        }
        p2.bs[6] = cum;
    }
    proj_all<2, __half><<<p2.bs[6], 256>>>(p2);

    // ---- layer 2: gathers ----
    gather_all<<<gatherBlocks, 256>>>(ga);

    // ---- final: combine2 + residual + l2norm ----
    const __half* HDst[3] = {Hm, Hd, Hc};
    const float* XRes[3] = {xm, xd, xc};
    const int resIdx[3] = {1, 2, 0};   // W_res rows: 0=c,1=m,2=d
    float* OT[3] = {Om, Od, Oc};
    Final3 f;
    {
        int cum = 0;
        for (int t = 0; t < 3; t++) {
            f.Hs[t]  = HDst[t];
            f.W2a[t] = W2r + (size_t)relA[t] * 4096;
            f.W2b[t] = W2r + (size_t)relB[t] * 4096;
            f.b2a[t] = b2 + (size_t)relA[t] * 64;
            f.b2b[t] = b2 + (size_t)relB[t] * 64;
            f.AGG[t] = AGGt[t];
            f.Xr[t]  = XRes[t];
            f.Wr[t]  = Wres + (size_t)resIdx[t] * 8192;
            f.br[t]  = bres + (size_t)resIdx[t] * 64;
            f.Y[t] = OT[t];
            f.M[t] = NT[t];
            f.bs[t] = cum; cum += (NT[t] + 127) / 128;
        }
        f.bs[3] = cum;
    }
    final_all<<<f.bs[3], 256>>>(f);
}

// round 15
// speedup vs baseline: 1.4117x; 1.4117x over previous
#include <cuda_runtime.h>
#include <cuda_fp16.h>
#include <cstddef>
#include <cstdint>

typedef unsigned long long ull;
typedef unsigned int uint;

// ---------------------------------------------------------------------------
// Problem constants
// ---------------------------------------------------------------------------
#define NC 100000
#define NM 50000
#define ND 10000

#define OFF_WORDS 320008ull
#define CSR_WORDS 4800000ull
#define P_WORDS   10240000ull      // P: 320k rows x 64 fp16 (counted in 4B words)
#define AGG_WORDS 10240000ull      // AGG: 160k rows x 64 fp32
#define HH_WORDS  5120000ull       // H: 160k rows x 64 fp16
#define SCRATCH_WORDS (OFF_WORDS + CSR_WORDS + P_WORDS + AGG_WORDS + HH_WORDS)
__device__ __align__(16) float g_scratch[SCRATCH_WORDS];

// ---------------------------------------------------------------------------
// f32x2 helpers (gather path)
// ---------------------------------------------------------------------------
__device__ __forceinline__ ull splat2(float x) {
    ull r; asm("mov.b64 %0, {%1, %1};" : "=l"(r) : "f"(x)); return r;
}
__device__ __forceinline__ ull pack2(float lo, float hi) {
    ull r; asm("mov.b64 %0, {%1, %2};" : "=l"(r) : "f"(lo), "f"(hi)); return r;
}
__device__ __forceinline__ ull add2(ull a, ull b) {
    ull r; asm("add.rn.f32x2 %0, %1, %2;" : "=l"(r) : "l"(a), "l"(b)); return r;
}
__device__ __forceinline__ ull mul2(ull a, ull b) {
    ull r; asm("mul.rn.f32x2 %0, %1, %2;" : "=l"(r) : "l"(a), "l"(b)); return r;
}
__device__ __forceinline__ ull h2_to_f2(uint h) {
    __half2 hv = *reinterpret_cast<__half2*>(&h);
    float2 f = __half22float2(hv);
    return pack2(f.x, f.y);
}

// ---------------------------------------------------------------------------
// mma / ldmatrix primitives
// ---------------------------------------------------------------------------
__device__ __forceinline__ void mma16816(float* c, const uint* a, const uint* b) {
    asm volatile(
        "mma.sync.aligned.m16n8k16.row.col.f32.f16.f16.f32 "
        "{%0,%1,%2,%3}, {%4,%5,%6,%7}, {%8,%9}, {%0,%1,%2,%3};"
        : "+f"(c[0]), "+f"(c[1]), "+f"(c[2]), "+f"(c[3])
        : "r"(a[0]), "r"(a[1]), "r"(a[2]), "r"(a[3]), "r"(b[0]), "r"(b[1]));
}
__device__ __forceinline__ void ldsm_x4(uint* r, uint32_t addr) {
    asm volatile("ldmatrix.sync.aligned.m8n8.x4.shared.b16 {%0,%1,%2,%3}, [%4];"
                 : "=r"(r[0]), "=r"(r[1]), "=r"(r[2]), "=r"(r[3]) : "r"(addr));
}
__device__ __forceinline__ void ldsm_x4_t(uint* r, uint32_t addr) {
    asm volatile("ldmatrix.sync.aligned.m8n8.x4.trans.shared.b16 {%0,%1,%2,%3}, [%4];"
                 : "=r"(r[0]), "=r"(r[1]), "=r"(r[2]), "=r"(r[3]) : "r"(addr));
}
__device__ __forceinline__ uint32_t smem_u32(const void* p) {
    return (uint32_t)__cvta_generic_to_shared(p);
}

// ---------------------------------------------------------------------------
// CSR build kernels (8 edges per thread)
// ---------------------------------------------------------------------------
__global__ void zero_int_kernel(int* __restrict__ p, int n) {
    int i = blockIdx.x * blockDim.x + threadIdx.x;
    if (i < n) p[i] = 0;
}

struct Edge6 {
    const int* src[6]; const int* dst[6];
    int* off[6]; int* csr[6];
    int bs[7]; int E[6];
};

__global__ void count_all(Edge6 a) {
    int b = blockIdx.x, r = 0;
    while (b >= a.bs[r + 1]) r++;
    int e = ((b - a.bs[r]) * 256 + threadIdx.x) * 8;
    int E = a.E[r];
    int* off = a.off[r];
    if (e + 8 <= E) {
        int4 d0 = *(const int4*)(a.dst[r] + e);
        int4 d1 = *(const int4*)(a.dst[r] + e + 4);
        atomicAdd(&off[d0.x + 1], 1);
        atomicAdd(&off[d0.y + 1], 1);
        atomicAdd(&off[d0.z + 1], 1);
        atomicAdd(&off[d0.w + 1], 1);
        atomicAdd(&off[d1.x + 1], 1);
        atomicAdd(&off[d1.y + 1], 1);
        atomicAdd(&off[d1.z + 1], 1);
        atomicAdd(&off[d1.w + 1], 1);
    } else {
        for (; e < E; e++) atomicAdd(&off[a.dst[r][e] + 1], 1);
    }
}

// Cursor-free fill: consumes the exclusive offsets in-place.
// After this kernel, off[d] == original off[d+1] (segment end).
__global__ void fill_all(Edge6 a) {
    int b = blockIdx.x, r = 0;
    while (b >= a.bs[r + 1]) r++;
    int e = ((b - a.bs[r]) * 256 + threadIdx.x) * 8;
    int E = a.E[r];
    int* off = a.off[r];
    int* csr = a.csr[r];
    if (e + 8 <= E) {
        int4 d0 = *(const int4*)(a.dst[r] + e);
        int4 d1 = *(const int4*)(a.dst[r] + e + 4);
        int4 s0 = *(const int4*)(a.src[r] + e);
        int4 s1 = *(const int4*)(a.src[r] + e + 4);
        csr[atomicAdd(&off[d0.x], 1)] = s0.x;
        csr[atomicAdd(&off[d0.y], 1)] = s0.y;
        csr[atomicAdd(&off[d0.z], 1)] = s0.z;
        csr[atomicAdd(&off[d0.w], 1)] = s0.w;
        csr[atomicAdd(&off[d1.x], 1)] = s1.x;
        csr[atomicAdd(&off[d1.y], 1)] = s1.y;
        csr[atomicAdd(&off[d1.z], 1)] = s1.z;
        csr[atomicAdd(&off[d1.w], 1)] = s1.w;
    } else {
        for (; e < E; e++)
            csr[atomicAdd(&off[a.dst[r][e]], 1)] = a.src[r][e];
    }
}

struct ScanArgs { int* data[6]; int n[6]; };

// One block per relation; inclusive scan of data[0..n] via warp shuffles.
__global__ __launch_bounds__(1024) void scan6(ScanArgs a) {
    __shared__ int wsum[33];
    int* data = a.data[blockIdx.x];
    int n = a.n[blockIdx.x];
    int t = threadIdx.x, lane = t & 31, wid = t >> 5;
    int carry = 0;
    for (int base = 0; base <= n; base += 4096) {
        int i0 = base + t * 4;
        int v0 = (i0     <= n) ? data[i0]     : 0;
        int v1 = (i0 + 1 <= n) ? data[i0 + 1] : 0;
        int v2 = (i0 + 2 <= n) ? data[i0 + 2] : 0;
        int v3 = (i0 + 3 <= n) ? data[i0 + 3] : 0;
        int s01 = v0 + v1;
        int s = s01 + v2 + v3;
        int sc = s;
        #pragma unroll
        for (int o = 1; o < 32; o <<= 1) {
            int u = __shfl_up_sync(0xffffffffu, sc, o);
            if (lane >= o) sc += u;
        }
        if (lane == 31) wsum[wid] = sc;
        __syncthreads();
        if (wid == 0) {
            int w = wsum[lane];
            int wc = w;
            #pragma unroll
            for (int o = 1; o < 32; o <<= 1) {
                int u = __shfl_up_sync(0xffffffffu, wc, o);
                if (lane >= o) wc += u;
            }
            wsum[lane] = wc;
            if (lane == 31) wsum[32] = wc;
        }
        __syncthreads();
        int prefix = carry + (wid ? wsum[wid - 1] : 0) + (sc - s);
        if (i0     <= n) data[i0]     = prefix + v0;
        if (i0 + 1 <= n) data[i0 + 1] = prefix + s01;
        if (i0 + 2 <= n) data[i0 + 2] = prefix + s01 + v2;
        if (i0 + 3 <= n) data[i0 + 3] = prefix + s;
        carry += wsum[32];
        __syncthreads();
    }
}

// ---------------------------------------------------------------------------
// Merged dual-relation gather (fp16 rows), one warp per dst node, 8-wide MLP.
// Post-fill offsets: segment of w is [w? off[w-1] : 0, off[w]).
// ---------------------------------------------------------------------------
__device__ __forceinline__ ull gather_rel(const __half* __restrict__ P,
                                          const int* __restrict__ off,
                                          const int* __restrict__ csr,
                                          int w, int lane, float& sc) {
    int s = w ? off[w - 1] : 0;
    int e = off[w];
    const uint* B = (const uint*)P + lane;
    ull a0 = 0ull, a1 = 0ull, a2 = 0ull, a3 = 0ull;
    int i = s;
    for (; i + 8 <= e; i += 8) {
        int s0 = csr[i],     s1 = csr[i + 1], s2 = csr[i + 2], s3 = csr[i + 3];
        int s4 = csr[i + 4], s5 = csr[i + 5], s6 = csr[i + 6], s7 = csr[i + 7];
        uint v0 = B[(size_t)s0 * 32];
        uint v1 = B[(size_t)s1 * 32];
        uint v2 = B[(size_t)s2 * 32];
        uint v3 = B[(size_t)s3 * 32];
        uint v4 = B[(size_t)s4 * 32];
        uint v5 = B[(size_t)s5 * 32];
        uint v6 = B[(size_t)s6 * 32];
        uint v7 = B[(size_t)s7 * 32];
        a0 = add2(a0, add2(h2_to_f2(v0), h2_to_f2(v1)));
        a1 = add2(a1, add2(h2_to_f2(v2), h2_to_f2(v3)));
        a2 = add2(a2, add2(h2_to_f2(v4), h2_to_f2(v5)));
        a3 = add2(a3, add2(h2_to_f2(v6), h2_to_f2(v7)));
    }
    for (; i < e; i++)
        a0 = add2(a0, h2_to_f2(B[(size_t)csr[i] * 32]));
    int deg = e - s;
    sc = 1.0f / (float)(deg > 1 ? deg : 1);
    return add2(add2(a0, a1), add2(a2, a3));
}

struct Gather3 {
    const __half* PA[3]; const int* offA[3]; const int* csrA[3];
    const __half* PB[3]; const int* offB[3]; const int* csrB[3];
    float* out[3]; int ws[4];
};

__global__ __launch_bounds__(256) void gather_all(Gather3 a) {
    int gw = (blockIdx.x * blockDim.x + threadIdx.x) >> 5;
    int lane = threadIdx.x & 31;
    if (gw >= a.ws[3]) return;
    int t = 0;
    while (gw >= a.ws[t + 1]) t++;
    int w = gw - a.ws[t];
    float scA, scB;
    ull accA = gather_rel(a.PA[t], a.offA[t], a.csrA[t], w, lane, scA);
    ull accB = gather_rel(a.PB[t], a.offB[t], a.csrB[t], w, lane, scB);
    ull res = add2(mul2(accA, splat2(scA)), mul2(accB, splat2(scB)));
    *(ull*)(a.out[t] + (size_t)w * 64 + lane * 2) = res;
}

// ---------------------------------------------------------------------------
// Tensor-core GEMM core, X dtype templated (float or __half source rows):
// acc += fp16(X[m0:m0+128, :kt*32]) @ fp16(wscale*(W0(+W1)))
// Block = 128 rows x 64 cols, 256 threads (8 warps x 16-row stripe).
// ---------------------------------------------------------------------------
#define XS 40
#define WS 72

template<typename T>
__device__ __forceinline__ void mma_tiles(
    const T* __restrict__ X, int ldx,
    const float* __restrict__ W0, const float* __restrict__ W1, float wscale,
    int ktiles, int m0, int M,
    __half Xh[][XS], __half Wh[][WS], float acc[8][4]) {

    const int t = threadIdx.x;
    const int lane = t & 31;
    const int wrow = (t >> 5) * 16;

    for (int kt = 0; kt < ktiles; kt++) {
        int kb = kt * 32;
        #pragma unroll
        for (int it = 0; it < 4; it++) {
            int idx = t + 256 * it;
            int row = idx >> 3, f4 = idx & 7;
            int m = m0 + row;
            if (sizeof(T) == 4) {
                float4 v = make_float4(0.f, 0.f, 0.f, 0.f);
                if (m < M) v = *(const float4*)((const float*)X + (size_t)m * ldx + kb + f4 * 4);
                __half2 h0 = __floats2half2_rn(v.x, v.y);
                __half2 h1 = __floats2half2_rn(v.z, v.w);
                uint2 st = { *(uint*)&h0, *(uint*)&h1 };
                *(uint2*)(&Xh[row][f4 * 4]) = st;
            } else {
                uint2 v = make_uint2(0u, 0u);
                if (m < M) v = *(const uint2*)((const __half*)X + (size_t)m * ldx + kb + f4 * 4);
                *(uint2*)(&Xh[row][f4 * 4]) = v;
            }
        }
        #pragma unroll
        for (int it = 0; it < 2; it++) {
            int idx = t + 256 * it;
            int kw = idx >> 4, f4 = idx & 15;
            const float* wp = W0 + (size_t)(kb + kw) * 64 + f4 * 4;
            float4 wv = *(const float4*)wp;
            if (W1) {
                float4 w2 = *(const float4*)(W1 + (size_t)(kb + kw) * 64 + f4 * 4);
                wv.x += w2.x; wv.y += w2.y; wv.z += w2.z; wv.w += w2.w;
            }
            wv.x *= wscale; wv.y *= wscale; wv.z *= wscale; wv.w *= wscale;
            __half2 h0 = __floats2half2_rn(wv.x, wv.y);
            __half2 h1 = __floats2half2_rn(wv.z, wv.w);
            uint2 st = { *(uint*)&h0, *(uint*)&h1 };
            *(uint2*)(&Wh[kw][f4 * 4]) = st;
        }
        __syncthreads();

        #pragma unroll
        for (int ks = 0; ks < 2; ks++) {
            int k = ks * 16;
            uint a[4];
            ldsm_x4(a, smem_u32(&Xh[wrow + (lane & 15)][k + (lane >> 4) * 8]));
            int i8 = lane & 7, sel = lane >> 3;
            #pragma unroll
            for (int jj = 0; jj < 4; jj++) {
                uint b[4];
                ldsm_x4_t(b, smem_u32(
                    &Wh[k + i8 + (sel & 1) * 8][jj * 16 + (sel >> 1) * 8]));
                mma16816(acc[jj * 2],     a, b);
                mma16816(acc[jj * 2 + 1], a, b + 2);
            }
        }
        __syncthreads();
    }
}

// ---------------------------------------------------------------------------
// proj_all: 6 independent projections Y[r] = fp16(X[r] @ W[r])
// ---------------------------------------------------------------------------
template<typename T>
struct Proj6 { const T* X[6]; const float* W[6]; __half* Y[6]; int M[6]; int bs[7]; };

template<int KT, typename T>
__global__ __launch_bounds__(256) void proj_all(Proj6<T> a) {
    __shared__ __half Xh[128][XS];
    __shared__ __half Wh[32][WS];
    int b = blockIdx.x, r = 0;
    while (b >= a.bs[r + 1]) r++;
    int m0 = (b - a.bs[r]) * 128;
    int M = a.M[r];

    float acc[8][4];
    #pragma unroll
    for (int i = 0; i < 8; i++)
        #pragma unroll
        for (int j = 0; j < 4; j++) acc[i][j] = 0.f;

    mma_tiles<T>(a.X[r], KT * 32, a.W[r], nullptr, 1.0f, KT, m0, M, Xh, Wh, acc);

    const int lane = threadIdx.x & 31;
    const int wrow = (threadIdx.x >> 5) * 16;
    const int q2 = (lane & 3) * 2;
    __half* Y = a.Y[r];
    #pragma unroll
    for (int half = 0; half < 2; half++) {
        int m = m0 + wrow + (lane >> 2) + half * 8;
        int off = half * 2;
        if (m < M) {
            #pragma unroll
            for (int j = 0; j < 8; j++) {
                __half2 h = __floats2half2_rn(acc[j][off], acc[j][off + 1]);
                *(uint*)(Y + (size_t)m * 64 + j * 8 + q2) = *(uint*)&h;
            }
        }
    }
}

// ---------------------------------------------------------------------------
// combine1_all: H(fp16) = relu(x @ 0.5(Wa+Wb) + 0.5*(AGG + ba + bb))
// ---------------------------------------------------------------------------
struct Comb3 {
    const float* X[3]; const float* Wa[3]; const float* Wb[3];
    const float* ba[3]; const float* bb[3]; const float* AGG[3];
    __half* Y[3]; int M[3]; int bs[4];
};

__global__ __launch_bounds__(256) void combine1_all(Comb3 a) {
    __shared__ __half Xh[128][XS];
    __shared__ __half Wh[32][WS];
    int b = blockIdx.x, t3 = 0;
    while (b >= a.bs[t3 + 1]) t3++;
    int m0 = (b - a.bs[t3]) * 128;
    int M = a.M[t3];

    float acc[8][4];
    #pragma unroll
    for (int i = 0; i < 8; i++)
        #pragma unroll
        for (int j = 0; j < 4; j++) acc[i][j] = 0.f;

    mma_tiles<float>(a.X[t3], 128, a.Wa[t3], a.Wb[t3], 0.5f, 4, m0, M, Xh, Wh, acc);

    const int lane = threadIdx.x & 31;
    const int wrow = (threadIdx.x >> 5) * 16;
    const int q2 = (lane & 3) * 2;
    const float* AGG = a.AGG[t3];
    __half* Y = a.Y[t3];
    float cb[8][2];
    #pragma unroll
    for (int j = 0; j < 8; j++) {
        int c = j * 8 + q2;
        cb[j][0] = 0.5f * (a.ba[t3][c] + a.bb[t3][c]);
        cb[j][1] = 0.5f * (a.ba[t3][c + 1] + a.bb[t3][c + 1]);
    }
    #pragma unroll
    for (int half = 0; half < 2; half++) {
        int m = m0 + wrow + (lane >> 2) + half * 8;
        int off = half * 2;
        if (m < M) {
            size_t base = (size_t)m * 64;
            #pragma unroll
            for (int j = 0; j < 8; j++) {
                int c = j * 8 + q2;
                float2 g = *(const float2*)(AGG + base + c);
                float ox = fmaxf(acc[j][off]     + 0.5f * g.x + cb[j][0], 0.f);
                float oy = fmaxf(acc[j][off + 1] + 0.5f * g.y + cb[j][1], 0.f);
                __half2 h = __floats2half2_rn(ox, oy);
                *(uint*)(Y + base + c) = *(uint*)&h;
            }
        }
    }
}

// ---------------------------------------------------------------------------
// final_all: O = l2norm( H @ 0.5(W2a+W2b) + 0.5*(AGG + b2a + b2b) + x@Wr + br )
// H is fp16.
// ---------------------------------------------------------------------------
struct Final3 {
    const __half* Hs[3]; const float* W2a[3]; const float* W2b[3];
    const float* b2a[3]; const float* b2b[3]; const float* AGG[3];
    const float* Xr[3]; const float* Wr[3]; const float* br[3];
    float* Y[3]; int M[3]; int bs[4];
};

__global__ __launch_bounds__(256) void final_all(Final3 a) {
    __shared__ __half Xh[128][XS];
    __shared__ __half Wh[32][WS];
    int b = blockIdx.x, t3 = 0;
    while (b >= a.bs[t3 + 1]) t3++;
    int m0 = (b - a.bs[t3]) * 128;
    int M = a.M[t3];

    float acc[8][4];
    #pragma unroll
    for (int i = 0; i < 8; i++)
        #pragma unroll
        for (int j = 0; j < 4; j++) acc[i][j] = 0.f;

    mma_tiles<__half>(a.Hs[t3], 64,  a.W2a[t3], a.W2b[t3], 0.5f, 2, m0, M, Xh, Wh, acc);
    mma_tiles<float>(a.Xr[t3], 128, a.Wr[t3],  nullptr,   1.0f, 4, m0, M, Xh, Wh, acc);

    const int lane = threadIdx.x & 31;
    const int wrow = (threadIdx.x >> 5) * 16;
    const int q2 = (lane & 3) * 2;
    const float* AGG = a.AGG[t3];
    float* Y = a.Y[t3];
    float cb[8][2];
    #pragma unroll
    for (int j = 0; j < 8; j++) {
        int c = j * 8 + q2;
        cb[j][0] = 0.5f * (a.b2a[t3][c] + a.b2b[t3][c]) + a.br[t3][c];
        cb[j][1] = 0.5f * (a.b2a[t3][c + 1] + a.b2b[t3][c + 1]) + a.br[t3][c + 1];
    }
    #pragma unroll
    for (int half = 0; half < 2; half++) {
        int m = m0 + wrow + (lane >> 2) + half * 8;
        int off = half * 2;
        bool ok = (m < M);
        size_t base = (size_t)m * 64;
        float v[8][2];
        float ss = 0.f;
        if (ok) {
            #pragma unroll
            for (int j = 0; j < 8; j++) {
                int c = j * 8 + q2;
                float2 g = *(const float2*)(AGG + base + c);
                v[j][0] = acc[j][off]     + 0.5f * g.x + cb[j][0];
                v[j][1] = acc[j][off + 1] + 0.5f * g.y + cb[j][1];
                ss += v[j][0] * v[j][0] + v[j][1] * v[j][1];
            }
        }
        ss += __shfl_xor_sync(0xffffffffu, ss, 1);
        ss += __shfl_xor_sync(0xffffffffu, ss, 2);
        if (ok) {
            float inv = 1.0f / fmaxf(sqrtf(ss), 1e-12f);
            #pragma unroll
            for (int j = 0; j < 8; j++) {
                float2 o = make_float2(v[j][0] * inv, v[j][1] * inv);
                *(float2*)(Y + base + j * 8 + q2) = o;
            }
        }
    }
}

// ---------------------------------------------------------------------------
// Host orchestration
// ---------------------------------------------------------------------------
extern "C" void kernel_launch(void* const* d_in, const int* in_sizes, int n_in,
                              void* d_out, int out_size) {
    static cudaStream_t s1 = [] {
        cudaStream_t s; cudaStreamCreateWithFlags(&s, cudaStreamNonBlocking); return s; }();
    static cudaEvent_t evFork = [] {
        cudaEvent_t e; cudaEventCreateWithFlags(&e, cudaEventDisableTiming); return e; }();
    static cudaEvent_t evJoin = [] {
        cudaEvent_t e; cudaEventCreateWithFlags(&e, cudaEventDisableTiming); return e; }();

    const float* xc = (const float*)d_in[0];
    const float* xm = (const float*)d_in[1];
    const float* xd = (const float*)d_in[2];
    // relation order: 0=c->m, 1=m->d, 2=c->d, 3=m->c, 4=d->m, 5=d->c
    const int srcIdx[6] = {3, 5, 7, 9, 11, 13};
    const int dstIdx[6] = {4, 6, 8, 10, 12, 14};
    const int* SRC[6]; const int* DST[6]; int EE[6];
    for (int r = 0; r < 6; r++) {
        SRC[r] = (const int*)d_in[srcIdx[r]];
        DST[r] = (const int*)d_in[dstIdx[r]];
        EE[r]  = in_sizes[srcIdx[r]];
    }
    const float* W1l  = (const float*)d_in[15];
    const float* W1r  = (const float*)d_in[16];
    const float* b1   = (const float*)d_in[17];
    const float* W2l  = (const float*)d_in[18];
    const float* W2r  = (const float*)d_in[19];
    const float* b2   = (const float*)d_in[20];
    const float* Wres = (const float*)d_in[21];
    const float* bres = (const float*)d_in[22];
    float* out = (float*)d_out;

    const int NSRC[6]    = {NC, NM, NC, NM, ND, ND};
    const int NDSTA[6]   = {NM, ND, ND, NC, NM, NC};
    const int srcType[6] = {0, 1, 0, 1, 2, 2};

    float* S = nullptr;
    cudaGetSymbolAddress((void**)&S, g_scratch);

    int*    OFF = (int*)S;
    int*    CSR = OFF + OFF_WORDS;
    __half* P   = (__half*)(CSR + CSR_WORDS);
    float*  AGG = (float*)(CSR + CSR_WORDS) + P_WORDS;
    __half* H   = (__half*)(AGG + AGG_WORDS);

    int* offR[6]; int* csrR[6]; __half* PR[6];
    {
        size_t o = 0, e = 0, p = 0;
        for (int r = 0; r < 6; r++) {
            offR[r] = OFF + o;  o += (size_t)NDSTA[r] + 1;
            csrR[r] = CSR + e;  e += (size_t)EE[r];
            PR[r]   = P + p;    p += (size_t)NSRC[r] * 64;
        }
    }

    float* AGGm = AGG;
    float* AGGd = AGGm + (size_t)NM * 64;
    float* AGGc = AGGd + (size_t)ND * 64;
    __half* Hc = H;
    __half* Hm = Hc + (size_t)NC * 64;
    __half* Hd = Hm + (size_t)NM * 64;
    const float* X1[3] = {xc, xm, xd};
    const __half* HX[3] = {Hc, Hm, Hd};
    float* Oc = out;
    float* Om = Oc + (size_t)NC * 64;
    float* Od = Om + (size_t)NM * 64;

    // ---- fork: CSR build on side stream ----
    cudaEventRecord(evFork, 0);
    cudaStreamWaitEvent(s1, evFork, 0);
    {
        int nz = (int)OFF_WORDS;
        zero_int_kernel<<<(nz + 255) / 256, 256, 0, s1>>>(OFF, nz);
    }
    Edge6 ea;
    {
        int cum = 0;
        for (int r = 0; r < 6; r++) {
            ea.src[r] = SRC[r]; ea.dst[r] = DST[r];
            ea.off[r] = offR[r]; ea.csr[r] = csrR[r];
            ea.E[r] = EE[r];
            ea.bs[r] = cum; cum += (EE[r] + 2047) / 2048;
        }
        ea.bs[6] = cum;
    }
    count_all<<<ea.bs[6], 256, 0, s1>>>(ea);
    {
        ScanArgs sa;
        for (int r = 0; r < 6; r++) { sa.data[r] = offR[r]; sa.n[r] = NDSTA[r]; }
        scan6<<<6, 1024, 0, s1>>>(sa);
    }
    fill_all<<<ea.bs[6], 256, 0, s1>>>(ea);
    cudaEventRecord(evJoin, s1);

    // ---- layer 1: projections (concurrent with CSR build) ----
    Proj6<float> p1;
    {
        int cum = 0;
        for (int r = 0; r < 6; r++) {
            p1.X[r] = X1[srcType[r]];
            p1.W[r] = W1l + (size_t)r * 8192;
            p1.Y[r] = PR[r];
            p1.M[r] = NSRC[r];
            p1.bs[r] = cum; cum += (NSRC[r] + 127) / 128;
        }
        p1.bs[6] = cum;
    }
    proj_all<4, float><<<p1.bs[6], 256>>>(p1);

    cudaStreamWaitEvent(0, evJoin, 0);

    // relation pairing per dst type: t=0 m <- (0,4); t=1 d <- (1,2); t=2 c <- (3,5)
    const int relA[3] = {0, 1, 3};
    const int relB[3] = {4, 2, 5};
    float* AGGt[3] = {AGGm, AGGd, AGGc};
    const int NT[3] = {NM, ND, NC};
    Gather3 ga;
    {
        int cum = 0;
        for (int t = 0; t < 3; t++) {
            ga.offA[t] = offR[relA[t]]; ga.csrA[t] = csrR[relA[t]];
            ga.offB[t] = offR[relB[t]]; ga.csrB[t] = csrR[relB[t]];
            ga.PA[t] = PR[relA[t]]; ga.PB[t] = PR[relB[t]];
            ga.out[t] = AGGt[t];
            ga.ws[t] = cum; cum += NT[t];
        }
        ga.ws[3] = cum;
    }
    const int gatherBlocks = ((NM + ND + NC) * 32 + 255) / 256;

    gather_all<<<gatherBlocks, 256>>>(ga);

    // ---- layer 1: combines (H in fp16) ----
    const float* XD[3] = {xm, xd, xc};
    __half* HT[3] = {Hm, Hd, Hc};
    Comb3 c1;
    {
        int cum = 0;
        for (int t = 0; t < 3; t++) {
            c1.X[t]  = XD[t];
            c1.Wa[t] = W1r + (size_t)relA[t] * 8192;
            c1.Wb[t] = W1r + (size_t)relB[t] * 8192;
            c1.ba[t] = b1 + (size_t)relA[t] * 64;
            c1.bb[t] = b1 + (size_t)relB[t] * 64;
            c1.AGG[t] = AGGt[t];
            c1.Y[t] = HT[t];
            c1.M[t] = NT[t];
            c1.bs[t] = cum; cum += (NT[t] + 127) / 128;
        }
        c1.bs[3] = cum;
    }
    combine1_all<<<c1.bs[3], 256>>>(c1);

    // ---- layer 2: projections (X = fp16 H) ----
    Proj6<__half> p2;
    {
        int cum = 0;
        for (int r = 0; r < 6; r++) {
            p2.X[r] = HX[srcType[r]];
            p2.W[r] = W2l + (size_t)r * 4096;
            p2.Y[r] = PR[r];
            p2.M[r] = NSRC[r];
            p2.bs[r] = cum; cum += (NSRC[r] + 127) / 128;
        }
        p2.bs[6] = cum;
    }
    proj_all<2, __half><<<p2.bs[6], 256>>>(p2);

    // ---- layer 2: gathers ----
    gather_all<<<gatherBlocks, 256>>>(ga);

    // ---- final: combine2 + residual + l2norm ----
    const __half* HDst[3] = {Hm, Hd, Hc};
    const float* XRes[3] = {xm, xd, xc};
    const int resIdx[3] = {1, 2, 0};   // W_res rows: 0=c,1=m,2=d
    float* OT[3] = {Om, Od, Oc};
    Final3 f;
    {
        int cum = 0;
        for (int t = 0; t < 3; t++) {
            f.Hs[t]  = HDst[t];
            f.W2a[t] = W2r + (size_t)relA[t] * 4096;
            f.W2b[t] = W2r + (size_t)relB[t] * 4096;
            f.b2a[t] = b2 + (size_t)relA[t] * 64;
            f.b2b[t] = b2 + (size_t)relB[t] * 64;
            f.AGG[t] = AGGt[t];
            f.Xr[t]  = XRes[t];
            f.Wr[t]  = Wres + (size_t)resIdx[t] * 8192;
            f.br[t]  = bres + (size_t)resIdx[t] * 64;
            f.Y[t] = OT[t];
            f.M[t] = NT[t];
            f.bs[t] = cum; cum += (NT[t] + 127) / 128;
        }
        f.bs[3] = cum;
    }
    final_all<<<f.bs[3], 256>>>(f);
}

// round 16
// speedup vs baseline: 1.4307x; 1.0134x over previous
#include <cuda_runtime.h>
#include <cuda_fp16.h>
#include <cstddef>
#include <cstdint>

typedef unsigned long long ull;
typedef unsigned int uint;

// ---------------------------------------------------------------------------
// Problem constants
// ---------------------------------------------------------------------------
#define NC 100000
#define NM 50000
#define ND 10000

#define OFF_WORDS 320008ull
#define CSR_WORDS 4800000ull
#define P_WORDS   10240000ull      // P: 320k rows x 64 fp16 (counted in 4B words)
#define AGG_WORDS 10240000ull      // AGG: 160k rows x 64 fp32
#define HH_WORDS  5120000ull       // H: 160k rows x 64 fp16
#define SCRATCH_WORDS (OFF_WORDS + CSR_WORDS + P_WORDS + AGG_WORDS + HH_WORDS)
__device__ __align__(16) float g_scratch[SCRATCH_WORDS];

// ---------------------------------------------------------------------------
// f32x2 helpers (gather path)
// ---------------------------------------------------------------------------
__device__ __forceinline__ ull splat2(float x) {
    ull r; asm("mov.b64 %0, {%1, %1};" : "=l"(r) : "f"(x)); return r;
}
__device__ __forceinline__ ull pack2(float lo, float hi) {
    ull r; asm("mov.b64 %0, {%1, %2};" : "=l"(r) : "f"(lo), "f"(hi)); return r;
}
__device__ __forceinline__ ull add2(ull a, ull b) {
    ull r; asm("add.rn.f32x2 %0, %1, %2;" : "=l"(r) : "l"(a), "l"(b)); return r;
}
__device__ __forceinline__ ull mul2(ull a, ull b) {
    ull r; asm("mul.rn.f32x2 %0, %1, %2;" : "=l"(r) : "l"(a), "l"(b)); return r;
}
__device__ __forceinline__ ull h2_to_f2(uint h) {
    __half2 hv = *reinterpret_cast<__half2*>(&h);
    float2 f = __half22float2(hv);
    return pack2(f.x, f.y);
}

// ---------------------------------------------------------------------------
// mma / ldmatrix primitives
// ---------------------------------------------------------------------------
__device__ __forceinline__ void mma16816(float* c, const uint* a, const uint* b) {
    asm volatile(
        "mma.sync.aligned.m16n8k16.row.col.f32.f16.f16.f32 "
        "{%0,%1,%2,%3}, {%4,%5,%6,%7}, {%8,%9}, {%0,%1,%2,%3};"
        : "+f"(c[0]), "+f"(c[1]), "+f"(c[2]), "+f"(c[3])
        : "r"(a[0]), "r"(a[1]), "r"(a[2]), "r"(a[3]), "r"(b[0]), "r"(b[1]));
}
__device__ __forceinline__ void ldsm_x4(uint* r, uint32_t addr) {
    asm volatile("ldmatrix.sync.aligned.m8n8.x4.shared.b16 {%0,%1,%2,%3}, [%4];"
                 : "=r"(r[0]), "=r"(r[1]), "=r"(r[2]), "=r"(r[3]) : "r"(addr));
}
__device__ __forceinline__ void ldsm_x4_t(uint* r, uint32_t addr) {
    asm volatile("ldmatrix.sync.aligned.m8n8.x4.trans.shared.b16 {%0,%1,%2,%3}, [%4];"
                 : "=r"(r[0]), "=r"(r[1]), "=r"(r[2]), "=r"(r[3]) : "r"(addr));
}
__device__ __forceinline__ uint32_t smem_u32(const void* p) {
    return (uint32_t)__cvta_generic_to_shared(p);
}

// ---------------------------------------------------------------------------
// CSR build kernels (8 edges per thread)
// ---------------------------------------------------------------------------
__global__ void zero_int_kernel(int* __restrict__ p, int n) {
    int i = blockIdx.x * blockDim.x + threadIdx.x;
    if (i < n) p[i] = 0;
}

struct Edge6 {
    const int* src[6]; const int* dst[6];
    int* off[6]; int* csr[6];
    int bs[7]; int E[6];
};

__global__ void count_all(Edge6 a) {
    int b = blockIdx.x, r = 0;
    while (b >= a.bs[r + 1]) r++;
    int e = ((b - a.bs[r]) * 256 + threadIdx.x) * 8;
    int E = a.E[r];
    int* off = a.off[r];
    if (e + 8 <= E) {
        int4 d0 = *(const int4*)(a.dst[r] + e);
        int4 d1 = *(const int4*)(a.dst[r] + e + 4);
        atomicAdd(&off[d0.x + 1], 1);
        atomicAdd(&off[d0.y + 1], 1);
        atomicAdd(&off[d0.z + 1], 1);
        atomicAdd(&off[d0.w + 1], 1);
        atomicAdd(&off[d1.x + 1], 1);
        atomicAdd(&off[d1.y + 1], 1);
        atomicAdd(&off[d1.z + 1], 1);
        atomicAdd(&off[d1.w + 1], 1);
    } else {
        for (; e < E; e++) atomicAdd(&off[a.dst[r][e] + 1], 1);
    }
}

// Cursor-free fill: consumes the exclusive offsets in-place.
// After this kernel, off[d] == original off[d+1] (segment end).
__global__ void fill_all(Edge6 a) {
    int b = blockIdx.x, r = 0;
    while (b >= a.bs[r + 1]) r++;
    int e = ((b - a.bs[r]) * 256 + threadIdx.x) * 8;
    int E = a.E[r];
    int* off = a.off[r];
    int* csr = a.csr[r];
    if (e + 8 <= E) {
        int4 d0 = *(const int4*)(a.dst[r] + e);
        int4 d1 = *(const int4*)(a.dst[r] + e + 4);
        int4 s0 = *(const int4*)(a.src[r] + e);
        int4 s1 = *(const int4*)(a.src[r] + e + 4);
        csr[atomicAdd(&off[d0.x], 1)] = s0.x;
        csr[atomicAdd(&off[d0.y], 1)] = s0.y;
        csr[atomicAdd(&off[d0.z], 1)] = s0.z;
        csr[atomicAdd(&off[d0.w], 1)] = s0.w;
        csr[atomicAdd(&off[d1.x], 1)] = s1.x;
        csr[atomicAdd(&off[d1.y], 1)] = s1.y;
        csr[atomicAdd(&off[d1.z], 1)] = s1.z;
        csr[atomicAdd(&off[d1.w], 1)] = s1.w;
    } else {
        for (; e < E; e++)
            csr[atomicAdd(&off[a.dst[r][e]], 1)] = a.src[r][e];
    }
}

struct ScanArgs { int* data[6]; int n[6]; };

// One block per relation; inclusive scan of data[0..n] via warp shuffles.
__global__ __launch_bounds__(1024) void scan6(ScanArgs a) {
    __shared__ int wsum[33];
    int* data = a.data[blockIdx.x];
    int n = a.n[blockIdx.x];
    int t = threadIdx.x, lane = t & 31, wid = t >> 5;
    int carry = 0;
    for (int base = 0; base <= n; base += 4096) {
        int i0 = base + t * 4;
        int v0 = (i0     <= n) ? data[i0]     : 0;
        int v1 = (i0 + 1 <= n) ? data[i0 + 1] : 0;
        int v2 = (i0 + 2 <= n) ? data[i0 + 2] : 0;
        int v3 = (i0 + 3 <= n) ? data[i0 + 3] : 0;
        int s01 = v0 + v1;
        int s = s01 + v2 + v3;
        int sc = s;
        #pragma unroll
        for (int o = 1; o < 32; o <<= 1) {
            int u = __shfl_up_sync(0xffffffffu, sc, o);
            if (lane >= o) sc += u;
        }
        if (lane == 31) wsum[wid] = sc;
        __syncthreads();
        if (wid == 0) {
            int w = wsum[lane];
            int wc = w;
            #pragma unroll
            for (int o = 1; o < 32; o <<= 1) {
                int u = __shfl_up_sync(0xffffffffu, wc, o);
                if (lane >= o) wc += u;
            }
            wsum[lane] = wc;
            if (lane == 31) wsum[32] = wc;
        }
        __syncthreads();
        int prefix = carry + (wid ? wsum[wid - 1] : 0) + (sc - s);
        if (i0     <= n) data[i0]     = prefix + v0;
        if (i0 + 1 <= n) data[i0 + 1] = prefix + s01;
        if (i0 + 2 <= n) data[i0 + 2] = prefix + s01 + v2;
        if (i0 + 3 <= n) data[i0 + 3] = prefix + s;
        carry += wsum[32];
        __syncthreads();
    }
}

// ---------------------------------------------------------------------------
// Merged dual-relation gather (fp16 rows), one warp per dst node, 8-wide MLP.
// Post-fill offsets: segment of w is [w? off[w-1] : 0, off[w]).
// ---------------------------------------------------------------------------
__device__ __forceinline__ ull gather_rel(const __half* __restrict__ P,
                                          const int* __restrict__ off,
                                          const int* __restrict__ csr,
                                          int w, int lane, float& sc) {
    int s = w ? off[w - 1] : 0;
    int e = off[w];
    const uint* B = (const uint*)P + lane;
    ull a0 = 0ull, a1 = 0ull, a2 = 0ull, a3 = 0ull;
    int i = s;
    for (; i + 8 <= e; i += 8) {
        int s0 = csr[i],     s1 = csr[i + 1], s2 = csr[i + 2], s3 = csr[i + 3];
        int s4 = csr[i + 4], s5 = csr[i + 5], s6 = csr[i + 6], s7 = csr[i + 7];
        uint v0 = B[(size_t)s0 * 32];
        uint v1 = B[(size_t)s1 * 32];
        uint v2 = B[(size_t)s2 * 32];
        uint v3 = B[(size_t)s3 * 32];
        uint v4 = B[(size_t)s4 * 32];
        uint v5 = B[(size_t)s5 * 32];
        uint v6 = B[(size_t)s6 * 32];
        uint v7 = B[(size_t)s7 * 32];
        a0 = add2(a0, add2(h2_to_f2(v0), h2_to_f2(v1)));
        a1 = add2(a1, add2(h2_to_f2(v2), h2_to_f2(v3)));
        a2 = add2(a2, add2(h2_to_f2(v4), h2_to_f2(v5)));
        a3 = add2(a3, add2(h2_to_f2(v6), h2_to_f2(v7)));
    }
    for (; i < e; i++)
        a0 = add2(a0, h2_to_f2(B[(size_t)csr[i] * 32]));
    int deg = e - s;
    sc = 1.0f / (float)(deg > 1 ? deg : 1);
    return add2(add2(a0, a1), add2(a2, a3));
}

struct Gather3 {
    const __half* PA[3]; const int* offA[3]; const int* csrA[3];
    const __half* PB[3]; const int* offB[3]; const int* csrB[3];
    float* out[3]; int ws[4];
};

__global__ __launch_bounds__(256) void gather_all(Gather3 a) {
    int gw = (blockIdx.x * blockDim.x + threadIdx.x) >> 5;
    int lane = threadIdx.x & 31;
    if (gw >= a.ws[3]) return;
    int t = 0;
    while (gw >= a.ws[t + 1]) t++;
    int w = gw - a.ws[t];
    float scA, scB;
    ull accA = gather_rel(a.PA[t], a.offA[t], a.csrA[t], w, lane, scA);
    ull accB = gather_rel(a.PB[t], a.offB[t], a.csrB[t], w, lane, scB);
    ull res = add2(mul2(accA, splat2(scA)), mul2(accB, splat2(scB)));
    *(ull*)(a.out[t] + (size_t)w * 64 + lane * 2) = res;
}

// ---------------------------------------------------------------------------
// Tensor-core GEMM core, X dtype templated (float or __half source rows):
// acc += fp16(X[m0:m0+128, :kt*32]) @ fp16(wscale*(W0(+W1)))
// Block = 128 rows x 64 cols, 256 threads (8 warps x 16-row stripe).
// ---------------------------------------------------------------------------
#define XS 40
#define WS 72

template<typename T>
__device__ __forceinline__ void mma_tiles(
    const T* __restrict__ X, int ldx,
    const float* __restrict__ W0, const float* __restrict__ W1, float wscale,
    int ktiles, int m0, int M,
    __half Xh[][XS], __half Wh[][WS], float acc[8][4]) {

    const int t = threadIdx.x;
    const int lane = t & 31;
    const int wrow = (t >> 5) * 16;

    for (int kt = 0; kt < ktiles; kt++) {
        int kb = kt * 32;
        #pragma unroll
        for (int it = 0; it < 4; it++) {
            int idx = t + 256 * it;
            int row = idx >> 3, f4 = idx & 7;
            int m = m0 + row;
            if (sizeof(T) == 4) {
                float4 v = make_float4(0.f, 0.f, 0.f, 0.f);
                if (m < M) v = *(const float4*)((const float*)X + (size_t)m * ldx + kb + f4 * 4);
                __half2 h0 = __floats2half2_rn(v.x, v.y);
                __half2 h1 = __floats2half2_rn(v.z, v.w);
                uint2 st = { *(uint*)&h0, *(uint*)&h1 };
                *(uint2*)(&Xh[row][f4 * 4]) = st;
            } else {
                uint2 v = make_uint2(0u, 0u);
                if (m < M) v = *(const uint2*)((const __half*)X + (size_t)m * ldx + kb + f4 * 4);
                *(uint2*)(&Xh[row][f4 * 4]) = v;
            }
        }
        #pragma unroll
        for (int it = 0; it < 2; it++) {
            int idx = t + 256 * it;
            int kw = idx >> 4, f4 = idx & 15;
            const float* wp = W0 + (size_t)(kb + kw) * 64 + f4 * 4;
            float4 wv = *(const float4*)wp;
            if (W1) {
                float4 w2 = *(const float4*)(W1 + (size_t)(kb + kw) * 64 + f4 * 4);
                wv.x += w2.x; wv.y += w2.y; wv.z += w2.z; wv.w += w2.w;
            }
            wv.x *= wscale; wv.y *= wscale; wv.z *= wscale; wv.w *= wscale;
            __half2 h0 = __floats2half2_rn(wv.x, wv.y);
            __half2 h1 = __floats2half2_rn(wv.z, wv.w);
            uint2 st = { *(uint*)&h0, *(uint*)&h1 };
            *(uint2*)(&Wh[kw][f4 * 4]) = st;
        }
        __syncthreads();

        #pragma unroll
        for (int ks = 0; ks < 2; ks++) {
            int k = ks * 16;
            uint a[4];
            ldsm_x4(a, smem_u32(&Xh[wrow + (lane & 15)][k + (lane >> 4) * 8]));
            int i8 = lane & 7, sel = lane >> 3;
            #pragma unroll
            for (int jj = 0; jj < 4; jj++) {
                uint b[4];
                ldsm_x4_t(b, smem_u32(
                    &Wh[k + i8 + (sel & 1) * 8][jj * 16 + (sel >> 1) * 8]));
                mma16816(acc[jj * 2],     a, b);
                mma16816(acc[jj * 2 + 1], a, b + 2);
            }
        }
        __syncthreads();
    }
}

// ---------------------------------------------------------------------------
// proj_all: 6 independent projections Y[r] = fp16(X[r] @ W[r])
// ---------------------------------------------------------------------------
template<typename T>
struct Proj6 { const T* X[6]; const float* W[6]; __half* Y[6]; int M[6]; int bs[7]; };

template<int KT, typename T>
__global__ __launch_bounds__(256) void proj_all(Proj6<T> a) {
    __shared__ __half Xh[128][XS];
    __shared__ __half Wh[32][WS];
    int b = blockIdx.x, r = 0;
    while (b >= a.bs[r + 1]) r++;
    int m0 = (b - a.bs[r]) * 128;
    int M = a.M[r];

    float acc[8][4];
    #pragma unroll
    for (int i = 0; i < 8; i++)
        #pragma unroll
        for (int j = 0; j < 4; j++) acc[i][j] = 0.f;

    mma_tiles<T>(a.X[r], KT * 32, a.W[r], nullptr, 1.0f, KT, m0, M, Xh, Wh, acc);

    const int lane = threadIdx.x & 31;
    const int wrow = (threadIdx.x >> 5) * 16;
    const int q2 = (lane & 3) * 2;
    __half* Y = a.Y[r];
    #pragma unroll
    for (int half = 0; half < 2; half++) {
        int m = m0 + wrow + (lane >> 2) + half * 8;
        int off = half * 2;
        if (m < M) {
            #pragma unroll
            for (int j = 0; j < 8; j++) {
                __half2 h = __floats2half2_rn(acc[j][off], acc[j][off + 1]);
                *(uint*)(Y + (size_t)m * 64 + j * 8 + q2) = *(uint*)&h;
            }
        }
    }
}

// ---------------------------------------------------------------------------
// combine1_all: H(fp16) = relu(x @ 0.5(Wa+Wb) + 0.5*(AGG + ba + bb))
// ---------------------------------------------------------------------------
struct Comb3 {
    const float* X[3]; const float* Wa[3]; const float* Wb[3];
    const float* ba[3]; const float* bb[3]; const float* AGG[3];
    __half* Y[3]; int M[3]; int bs[4];
};

__global__ __launch_bounds__(256) void combine1_all(Comb3 a) {
    __shared__ __half Xh[128][XS];
    __shared__ __half Wh[32][WS];
    int b = blockIdx.x, t3 = 0;
    while (b >= a.bs[t3 + 1]) t3++;
    int m0 = (b - a.bs[t3]) * 128;
    int M = a.M[t3];

    float acc[8][4];
    #pragma unroll
    for (int i = 0; i < 8; i++)
        #pragma unroll
        for (int j = 0; j < 4; j++) acc[i][j] = 0.f;

    mma_tiles<float>(a.X[t3], 128, a.Wa[t3], a.Wb[t3], 0.5f, 4, m0, M, Xh, Wh, acc);

    const int lane = threadIdx.x & 31;
    const int wrow = (threadIdx.x >> 5) * 16;
    const int q2 = (lane & 3) * 2;
    const float* AGG = a.AGG[t3];
    __half* Y = a.Y[t3];
    float cb[8][2];
    #pragma unroll
    for (int j = 0; j < 8; j++) {
        int c = j * 8 + q2;
        cb[j][0] = 0.5f * (a.ba[t3][c] + a.bb[t3][c]);
        cb[j][1] = 0.5f * (a.ba[t3][c + 1] + a.bb[t3][c + 1]);
    }
    #pragma unroll
    for (int half = 0; half < 2; half++) {
        int m = m0 + wrow + (lane >> 2) + half * 8;
        int off = half * 2;
        if (m < M) {
            size_t base = (size_t)m * 64;
            #pragma unroll
            for (int j = 0; j < 8; j++) {
                int c = j * 8 + q2;
                float2 g = *(const float2*)(AGG + base + c);
                float ox = fmaxf(acc[j][off]     + 0.5f * g.x + cb[j][0], 0.f);
                float oy = fmaxf(acc[j][off + 1] + 0.5f * g.y + cb[j][1], 0.f);
                __half2 h = __floats2half2_rn(ox, oy);
                *(uint*)(Y + base + c) = *(uint*)&h;
            }
        }
    }
}

// ---------------------------------------------------------------------------
// final_all: O = l2norm( H @ 0.5(W2a+W2b) + 0.5*(AGG + b2a + b2b) + x@Wr + br )
// H is fp16.
// ---------------------------------------------------------------------------
struct Final3 {
    const __half* Hs[3]; const float* W2a[3]; const float* W2b[3];
    const float* b2a[3]; const float* b2b[3]; const float* AGG[3];
    const float* Xr[3]; const float* Wr[3]; const float* br[3];
    float* Y[3]; int M[3]; int bs[4];
};

__global__ __launch_bounds__(256) void final_all(Final3 a) {
    __shared__ __half Xh[128][XS];
    __shared__ __half Wh[32][WS];
    int b = blockIdx.x, t3 = 0;
    while (b >= a.bs[t3 + 1]) t3++;
    int m0 = (b - a.bs[t3]) * 128;
    int M = a.M[t3];

    float acc[8][4];
    #pragma unroll
    for (int i = 0; i < 8; i++)
        #pragma unroll
        for (int j = 0; j < 4; j++) acc[i][j] = 0.f;

    mma_tiles<__half>(a.Hs[t3], 64,  a.W2a[t3], a.W2b[t3], 0.5f, 2, m0, M, Xh, Wh, acc);
    mma_tiles<float>(a.Xr[t3], 128, a.Wr[t3],  nullptr,   1.0f, 4, m0, M, Xh, Wh, acc);

    const int lane = threadIdx.x & 31;
    const int wrow = (threadIdx.x >> 5) * 16;
    const int q2 = (lane & 3) * 2;
    const float* AGG = a.AGG[t3];
    float* Y = a.Y[t3];
    float cb[8][2];
    #pragma unroll
    for (int j = 0; j < 8; j++) {
        int c = j * 8 + q2;
        cb[j][0] = 0.5f * (a.b2a[t3][c] + a.b2b[t3][c]) + a.br[t3][c];
        cb[j][1] = 0.5f * (a.b2a[t3][c + 1] + a.b2b[t3][c + 1]) + a.br[t3][c + 1];
    }
    #pragma unroll
    for (int half = 0; half < 2; half++) {
        int m = m0 + wrow + (lane >> 2) + half * 8;
        int off = half * 2;
        bool ok = (m < M);
        size_t base = (size_t)m * 64;
        float v[8][2];
        float ss = 0.f;
        if (ok) {
            #pragma unroll
            for (int j = 0; j < 8; j++) {
                int c = j * 8 + q2;
                float2 g = *(const float2*)(AGG + base + c);
                v[j][0] = acc[j][off]     + 0.5f * g.x + cb[j][0];
                v[j][1] = acc[j][off + 1] + 0.5f * g.y + cb[j][1];
                ss += v[j][0] * v[j][0] + v[j][1] * v[j][1];
            }
        }
        ss += __shfl_xor_sync(0xffffffffu, ss, 1);
        ss += __shfl_xor_sync(0xffffffffu, ss, 2);
        if (ok) {
            float inv = 1.0f / fmaxf(sqrtf(ss), 1e-12f);
            #pragma unroll
            for (int j = 0; j < 8; j++) {
                float2 o = make_float2(v[j][0] * inv, v[j][1] * inv);
                *(float2*)(Y + base + j * 8 + q2) = o;
            }
        }
    }
}

// ---------------------------------------------------------------------------
// Host orchestration
// ---------------------------------------------------------------------------
extern "C" void kernel_launch(void* const* d_in, const int* in_sizes, int n_in,
                              void* d_out, int out_size) {
    static cudaStream_t s1 = [] {
        cudaStream_t s; cudaStreamCreateWithFlags(&s, cudaStreamNonBlocking); return s; }();
    static cudaEvent_t evFork = [] {
        cudaEvent_t e; cudaEventCreateWithFlags(&e, cudaEventDisableTiming); return e; }();
    static cudaEvent_t evJoin = [] {
        cudaEvent_t e; cudaEventCreateWithFlags(&e, cudaEventDisableTiming); return e; }();

    const float* xc = (const float*)d_in[0];
    const float* xm = (const float*)d_in[1];
    const float* xd = (const float*)d_in[2];
    // relation order: 0=c->m, 1=m->d, 2=c->d, 3=m->c, 4=d->m, 5=d->c
    const int srcIdx[6] = {3, 5, 7, 9, 11, 13};
    const int dstIdx[6] = {4, 6, 8, 10, 12, 14};
    const int* SRC[6]; const int* DST[6]; int EE[6];
    for (int r = 0; r < 6; r++) {
        SRC[r] = (const int*)d_in[srcIdx[r]];
        DST[r] = (const int*)d_in[dstIdx[r]];
        EE[r]  = in_sizes[srcIdx[r]];
    }
    const float* W1l  = (const float*)d_in[15];
    const float* W1r  = (const float*)d_in[16];
    const float* b1   = (const float*)d_in[17];
    const float* W2l  = (const float*)d_in[18];
    const float* W2r  = (const float*)d_in[19];
    const float* b2   = (const float*)d_in[20];
    const float* Wres = (const float*)d_in[21];
    const float* bres = (const float*)d_in[22];
    float* out = (float*)d_out;

    const int NSRC[6]    = {NC, NM, NC, NM, ND, ND};
    const int NDSTA[6]   = {NM, ND, ND, NC, NM, NC};
    const int srcType[6] = {0, 1, 0, 1, 2, 2};

    float* S = nullptr;
    cudaGetSymbolAddress((void**)&S, g_scratch);

    int*    OFF = (int*)S;
    int*    CSR = OFF + OFF_WORDS;
    __half* P   = (__half*)(CSR + CSR_WORDS);
    float*  AGG = (float*)(CSR + CSR_WORDS) + P_WORDS;
    __half* H   = (__half*)(AGG + AGG_WORDS);

    int* offR[6]; int* csrR[6]; __half* PR[6];
    {
        size_t o = 0, e = 0, p = 0;
        for (int r = 0; r < 6; r++) {
            offR[r] = OFF + o;  o += (size_t)NDSTA[r] + 1;
            csrR[r] = CSR + e;  e += (size_t)EE[r];
            PR[r]   = P + p;    p += (size_t)NSRC[r] * 64;
        }
    }

    float* AGGm = AGG;
    float* AGGd = AGGm + (size_t)NM * 64;
    float* AGGc = AGGd + (size_t)ND * 64;
    __half* Hc = H;
    __half* Hm = Hc + (size_t)NC * 64;
    __half* Hd = Hm + (size_t)NM * 64;
    const float* X1[3] = {xc, xm, xd};
    const __half* HX[3] = {Hc, Hm, Hd};
    float* Oc = out;
    float* Om = Oc + (size_t)NC * 64;
    float* Od = Om + (size_t)NM * 64;

    // ---- fork: CSR build on side stream ----
    cudaEventRecord(evFork, 0);
    cudaStreamWaitEvent(s1, evFork, 0);
    {
        int nz = (int)OFF_WORDS;
        zero_int_kernel<<<(nz + 255) / 256, 256, 0, s1>>>(OFF, nz);
    }
    Edge6 ea;
    {
        int cum = 0;
        for (int r = 0; r < 6; r++) {
            ea.src[r] = SRC[r]; ea.dst[r] = DST[r];
            ea.off[r] = offR[r]; ea.csr[r] = csrR[r];
            ea.E[r] = EE[r];
            ea.bs[r] = cum; cum += (EE[r] + 2047) / 2048;
        }
        ea.bs[6] = cum;
    }
    count_all<<<ea.bs[6], 256, 0, s1>>>(ea);
    {
        ScanArgs sa;
        for (int r = 0; r < 6; r++) { sa.data[r] = offR[r]; sa.n[r] = NDSTA[r]; }
        scan6<<<6, 1024, 0, s1>>>(sa);
    }
    fill_all<<<ea.bs[6], 256, 0, s1>>>(ea);
    cudaEventRecord(evJoin, s1);

    // ---- layer 1: projections (concurrent with CSR build) ----
    Proj6<float> p1;
    {
        int cum = 0;
        for (int r = 0; r < 6; r++) {
            p1.X[r] = X1[srcType[r]];
            p1.W[r] = W1l + (size_t)r * 8192;
            p1.Y[r] = PR[r];
            p1.M[r] = NSRC[r];
            p1.bs[r] = cum; cum += (NSRC[r] + 127) / 128;
        }
        p1.bs[6] = cum;
    }
    proj_all<4, float><<<p1.bs[6], 256>>>(p1);

    cudaStreamWaitEvent(0, evJoin, 0);

    // relation pairing per dst type: t=0 m <- (0,4); t=1 d <- (1,2); t=2 c <- (3,5)
    const int relA[3] = {0, 1, 3};
    const int relB[3] = {4, 2, 5};
    float* AGGt[3] = {AGGm, AGGd, AGGc};
    const int NT[3] = {NM, ND, NC};
    Gather3 ga;
    {
        int cum = 0;
        for (int t = 0; t < 3; t++) {
            ga.offA[t] = offR[relA[t]]; ga.csrA[t] = csrR[relA[t]];
            ga.offB[t] = offR[relB[t]]; ga.csrB[t] = csrR[relB[t]];
            ga.PA[t] = PR[relA[t]]; ga.PB[t] = PR[relB[t]];
            ga.out[t] = AGGt[t];
            ga.ws[t] = cum; cum += NT[t];
        }
        ga.ws[3] = cum;
    }
    const int gatherBlocks = ((NM + ND + NC) * 32 + 255) / 256;

    gather_all<<<gatherBlocks, 256>>>(ga);

    // ---- layer 1: combines (H in fp16) ----
    const float* XD[3] = {xm, xd, xc};
    __half* HT[3] = {Hm, Hd, Hc};
    Comb3 c1;
    {
        int cum = 0;
        for (int t = 0; t < 3; t++) {
            c1.X[t]  = XD[t];
            c1.Wa[t] = W1r + (size_t)relA[t] * 8192;
            c1.Wb[t] = W1r + (size_t)relB[t] * 8192;
            c1.ba[t] = b1 + (size_t)relA[t] * 64;
            c1.bb[t] = b1 + (size_t)relB[t] * 64;
            c1.AGG[t] = AGGt[t];
            c1.Y[t] = HT[t];
            c1.M[t] = NT[t];
            c1.bs[t] = cum; cum += (NT[t] + 127) / 128;
        }
        c1.bs[3] = cum;
    }
    combine1_all<<<c1.bs[3], 256>>>(c1);

    // ---- layer 2: projections (X = fp16 H) ----
    Proj6<__half> p2;
    {
        int cum = 0;
        for (int r = 0; r < 6; r++) {
            p2.X[r] = HX[srcType[r]];
            p2.W[r] = W2l + (size_t)r * 4096;
            p2.Y[r] = PR[r];
            p2.M[r] = NSRC[r];
            p2.bs[r] = cum; cum += (NSRC[r] + 127) / 128;
        }
        p2.bs[6] = cum;
    }
    proj_all<2, __half><<<p2.bs[6], 256>>>(p2);

    // ---- layer 2: gathers ----
    gather_all<<<gatherBlocks, 256>>>(ga);

    // ---- final: combine2 + residual + l2norm ----
    const __half* HDst[3] = {Hm, Hd, Hc};
    const float* XRes[3] = {xm, xd, xc};
    const int resIdx[3] = {1, 2, 0};   // W_res rows: 0=c,1=m,2=d
    float* OT[3] = {Om, Od, Oc};
    Final3 f;
    {
        int cum = 0;
        for (int t = 0; t < 3; t++) {
            f.Hs[t]  = HDst[t];
            f.W2a[t] = W2r + (size_t)relA[t] * 4096;
            f.W2b[t] = W2r + (size_t)relB[t] * 4096;
            f.b2a[t] = b2 + (size_t)relA[t] * 64;
            f.b2b[t] = b2 + (size_t)relB[t] * 64;
            f.AGG[t] = AGGt[t];
            f.Xr[t]  = XRes[t];
            f.Wr[t]  = Wres + (size_t)resIdx[t] * 8192;
            f.br[t]  = bres + (size_t)resIdx[t] * 64;
            f.Y[t] = OT[t];
            f.M[t] = NT[t];
            f.bs[t] = cum; cum += (NT[t] + 127) / 128;
        }
        f.bs[3] = cum;
    }
    final_all<<<f.bs[3], 256>>>(f);
}